// round 4
// baseline (speedup 1.0000x reference)
#include <cuda_runtime.h>
#include <cuda_bf16.h>
#include <cstdint>

#define MAX_N 100000

// Packed bf16 hi/lo intermediates: u32 = hi | (lo<<16)
__device__ __align__(16) uint32_t g_mid1p[MAX_N * 64];
__device__ __align__(16) uint32_t g_mid2p[MAX_N * 64];
// Pre-split weights (transposed to [n][k])
__device__ __align__(16) uint32_t g_w1p[64 * 256];
__device__ __align__(16) uint32_t g_w2p[9 * 64 * 64];
__device__ __align__(16) uint32_t g_w3p[256 * 64];

// ---------------- helpers ----------------
__device__ __forceinline__ uint32_t prmt(uint32_t a, uint32_t b, uint32_t s) {
    uint32_t d; asm("prmt.b32 %0,%1,%2,%3;" : "=r"(d) : "r"(a), "r"(b), "r"(s)); return d;
}
__device__ __forceinline__ uint32_t packf(float x) {
    __nv_bfloat16 h = __float2bfloat16(x);
    __nv_bfloat16 l = __float2bfloat16(x - __bfloat162float(h));
    return (uint32_t)__bfloat16_as_ushort(h) | ((uint32_t)__bfloat16_as_ushort(l) << 16);
}
__device__ __forceinline__ uint4 pack4(float4 v) {
    uint4 o; o.x = packf(v.x); o.y = packf(v.y); o.z = packf(v.z); o.w = packf(v.w); return o;
}
__device__ __forceinline__ uint32_t smem_u32(const void* p) {
    uint32_t a;
    asm("{ .reg .u64 t; cvta.to.shared.u64 t, %1; cvt.u32.u64 %0, t; }" : "=r"(a) : "l"(p));
    return a;
}
__device__ __forceinline__ void cpa16(uint32_t dst, const void* src, int srcsize) {
    asm volatile("cp.async.cg.shared.global [%0], [%1], 16, %2;"
                 :: "r"(dst), "l"(src), "r"(srcsize));
}
#define CP_COMMIT() asm volatile("cp.async.commit_group;" ::: "memory")
#define CP_WAIT1()  asm volatile("cp.async.wait_group 1;" ::: "memory")

__device__ __forceinline__ void mma_bf16(float* c, uint32_t a0, uint32_t a1, uint32_t a2,
                                         uint32_t a3, uint32_t b0, uint32_t b1) {
    asm volatile(
        "mma.sync.aligned.m16n8k16.row.col.f32.bf16.bf16.f32 "
        "{%0,%1,%2,%3}, {%4,%5,%6,%7}, {%8,%9}, {%0,%1,%2,%3};"
        : "+f"(c[0]), "+f"(c[1]), "+f"(c[2]), "+f"(c[3])
        : "r"(a0), "r"(a1), "r"(a2), "r"(a3), "r"(b0), "r"(b1));
}

struct AFrag { uint32_t hi[4], lo[4]; };
struct BFrag { uint32_t hi[2], lo[2]; };

__device__ __forceinline__ AFrag load_a(const uint32_t* A, int S, int row0, int k0, int g, int tg) {
    const uint32_t* p = A + (row0 + g) * S + k0 + 2 * tg;
    uint2 q0 = *(const uint2*)p;
    uint2 q1 = *(const uint2*)(p + 8 * S);
    uint2 q2 = *(const uint2*)(p + 8);
    uint2 q3 = *(const uint2*)(p + 8 * S + 8);
    AFrag f;
    f.hi[0] = prmt(q0.x, q0.y, 0x5410); f.lo[0] = prmt(q0.x, q0.y, 0x7632);
    f.hi[1] = prmt(q1.x, q1.y, 0x5410); f.lo[1] = prmt(q1.x, q1.y, 0x7632);
    f.hi[2] = prmt(q2.x, q2.y, 0x5410); f.lo[2] = prmt(q2.x, q2.y, 0x7632);
    f.hi[3] = prmt(q3.x, q3.y, 0x5410); f.lo[3] = prmt(q3.x, q3.y, 0x7632);
    return f;
}
__device__ __forceinline__ BFrag load_b(const uint32_t* B, int S, int n0, int k0, int g, int tg) {
    const uint32_t* p = B + (n0 + g) * S + k0 + 2 * tg;
    uint2 r0 = *(const uint2*)p;
    uint2 r1 = *(const uint2*)(p + 8);
    BFrag f;
    f.hi[0] = prmt(r0.x, r0.y, 0x5410); f.lo[0] = prmt(r0.x, r0.y, 0x7632);
    f.hi[1] = prmt(r1.x, r1.y, 0x5410); f.lo[1] = prmt(r1.x, r1.y, 0x7632);
    return f;
}
__device__ __forceinline__ void mma3(float* c, const AFrag& a, const BFrag& b) {
    mma_bf16(c, a.hi[0], a.hi[1], a.hi[2], a.hi[3], b.hi[0], b.hi[1]);
    mma_bf16(c, a.hi[0], a.hi[1], a.hi[2], a.hi[3], b.lo[0], b.lo[1]);
    mma_bf16(c, a.lo[0], a.lo[1], a.lo[2], a.lo[3], b.hi[0], b.hi[1]);
}

// ---------------- prep: split weights, transpose to [n][k] ----------------
__global__ void prep_weights(const float* __restrict__ w1, const float* __restrict__ w2,
                             const float* __restrict__ w3) {
    int tid = blockIdx.x * blockDim.x + threadIdx.x;
    int nt = gridDim.x * blockDim.x;
    for (int i = tid; i < 64 * 256; i += nt) {
        int n = i >> 8, k = i & 255;
        g_w1p[i] = packf(w1[k * 64 + n]);
    }
    for (int i = tid; i < 9 * 64 * 64; i += nt) {
        int ko = i >> 12, r = i & 4095, n = r >> 6, k = r & 63;
        g_w2p[i] = packf(w2[ko * 4096 + k * 64 + n]);
    }
    for (int i = tid; i < 256 * 64; i += nt) {
        int n = i >> 6, k = i & 63;
        g_w3p[i] = packf(w3[k * 256 + n]);
    }
}

// ===========================================================================
// conv1: K=256 in 4 panels of 64, register-prefetch pipeline, 1 sync/panel.
// smem: B[64][260] (66.6KB) + A 2x[128][68] (69.6KB) = 136,192 B
// ===========================================================================
__global__ void __launch_bounds__(512) conv1_k(
    const float* __restrict__ feat, const float* __restrict__ scale,
    const float* __restrict__ bias, int N, int tiles)
{
    extern __shared__ uint32_t sm[];
    uint32_t* Bsm = sm;                   // stride 260
    uint32_t* Asm = sm + 64 * 260;        // 2 panels, stride 68
    const int tid = threadIdx.x, w = tid >> 5, lane = tid & 31;
    const int g = lane >> 2, tg = lane & 3;
    const int m0w = (w & 3) * 32, n0w = (w >> 2) * 16;
    const int sr = tid >> 2, sq = tid & 3;    // 4 threads/row, 16 floats each

    for (int e = tid; e < 4096; e += 512) {
        uint4 v = ((const uint4*)g_w1p)[e];
        int n = e >> 6, kq = e & 63;
        *(uint4*)(Bsm + n * 260 + kq * 4) = v;
    }

    float4 nx[4];
    // prologue: load tile0 panel0
    {
        int grow = (blockIdx.x << 7) + sr;
        if (grow < N) {
            const float4* s = (const float4*)(feat + (size_t)grow * 256 + sq * 16);
            nx[0] = s[0]; nx[1] = s[1]; nx[2] = s[2]; nx[3] = s[3];
        } else nx[0] = nx[1] = nx[2] = nx[3] = make_float4(0.f, 0.f, 0.f, 0.f);
    }
    __syncthreads();   // B staged

    for (int t = blockIdx.x; t < tiles; t += gridDim.x) {
        const int row0 = t << 7;
        float C[2][2][4] = {};
        #pragma unroll
        for (int p = 0; p < 4; p++) {
            uint32_t* buf = Asm + (p & 1) * 8704;
            {   // store current panel (regs -> smem)
                uint32_t* d = buf + sr * 68 + sq * 16;
                *(uint4*)(d)      = pack4(nx[0]);
                *(uint4*)(d + 4)  = pack4(nx[1]);
                *(uint4*)(d + 8)  = pack4(nx[2]);
                *(uint4*)(d + 12) = pack4(nx[3]);
            }
            __syncthreads();
            {   // prefetch next panel
                int tn = (p < 3) ? t : t + gridDim.x;
                int pn = (p < 3) ? p + 1 : 0;
                int grow = (tn << 7) + sr;
                if (grow < N) {
                    const float4* s = (const float4*)(feat + (size_t)grow * 256 + pn * 64 + sq * 16);
                    nx[0] = s[0]; nx[1] = s[1]; nx[2] = s[2]; nx[3] = s[3];
                } else nx[0] = nx[1] = nx[2] = nx[3] = make_float4(0.f, 0.f, 0.f, 0.f);
            }
            #pragma unroll
            for (int s = 0; s < 4; s++) {
                int kl = s * 16;
                AFrag a0 = load_a(buf, 68, m0w, kl, g, tg);
                AFrag a1 = load_a(buf, 68, m0w + 16, kl, g, tg);
                BFrag b0 = load_b(Bsm, 260, n0w, p * 64 + kl, g, tg);
                BFrag b1 = load_b(Bsm, 260, n0w + 8, p * 64 + kl, g, tg);
                mma3(C[0][0], a0, b0); mma3(C[0][1], a0, b1);
                mma3(C[1][0], a1, b0); mma3(C[1][1], a1, b1);
            }
        }
        #pragma unroll
        for (int mf = 0; mf < 2; mf++)
        #pragma unroll
        for (int nf = 0; nf < 2; nf++) {
            int row = row0 + m0w + mf * 16 + g;
            int col = n0w + nf * 8 + 2 * tg;
            float s0 = __ldg(scale + col), s1 = __ldg(scale + col + 1);
            float bb0 = __ldg(bias + col), bb1 = __ldg(bias + col + 1);
            if (row < N) {
                uint2 o;
                o.x = packf(fmaxf(fmaf(C[mf][nf][0], s0, bb0), 0.f));
                o.y = packf(fmaxf(fmaf(C[mf][nf][1], s1, bb1), 0.f));
                *(uint2*)(g_mid1p + (size_t)row * 64 + col) = o;
            }
            if (row + 8 < N) {
                uint2 o;
                o.x = packf(fmaxf(fmaf(C[mf][nf][2], s0, bb0), 0.f));
                o.y = packf(fmaxf(fmaf(C[mf][nf][3], s1, bb1), 0.f));
                *(uint2*)(g_mid1p + (size_t)(row + 8) * 64 + col) = o;
            }
        }
    }
}

// ===========================================================================
// conv2: cp.async double-buffered gather, issued one ko ahead.
// smem: B 9x[64][68] (156.7KB) + A 2x[128][68] (69.6KB) = 226,304 B
// ===========================================================================
__global__ void __launch_bounds__(512) conv2_k(
    const int* __restrict__ nbr, const float* __restrict__ scale,
    const float* __restrict__ bias, int N, int tiles)
{
    extern __shared__ uint32_t sm[];
    uint32_t* Bsm = sm;                    // [ko][64][68]
    uint32_t* Asm = sm + 9 * 4352;         // 2 x [128][68]
    const uint32_t smb = smem_u32(sm);
    const uint32_t Ab = smb + 9 * 4352 * 4;
    const int tid = threadIdx.x, w = tid >> 5, lane = tid & 31;
    const int g = lane >> 2, tg = lane & 3;
    const int m0w = (w & 3) * 32, n0w = (w >> 2) * 16;
    const int sr = tid >> 2, sq = tid & 3;    // 4 thr/row, 4x16B each

    for (int e = tid; e < 9216; e += 512) {
        uint4 v = ((const uint4*)g_w2p)[e];
        int ko = e >> 10, r = e & 1023, n = r >> 4, kq = r & 15;
        *(uint4*)(Bsm + ko * 4352 + n * 68 + kq * 4) = v;
    }
    __syncthreads();

    const uint32_t dst_row = Ab + (sr * 68 + sq * 16) * 4;

    for (int t = blockIdx.x; t < tiles; t += gridDim.x) {
        const int row0 = t << 7;
        const int grow = row0 + sr;
        int nidx9[9];
        #pragma unroll
        for (int ko = 0; ko < 9; ko++)
            nidx9[ko] = (grow < N) ? __ldg(nbr + (size_t)grow * 9 + ko) : N;

        // prologue gather ko=0 -> buf0
        {
            int nn = nidx9[0];
            int sz = (nn < N) ? 16 : 0;
            const uint32_t* src = g_mid1p + (size_t)(nn < N ? nn : 0) * 64 + sq * 16;
            #pragma unroll
            for (int j = 0; j < 4; j++) cpa16(dst_row + j * 16, src + j * 4, sz);
            CP_COMMIT();
        }

        float C[2][2][4] = {};
        #pragma unroll
        for (int ko = 0; ko < 9; ko++) {
            // gather ko+1 into other buffer (dummy zero-fill at ko=8)
            {
                int nn = (ko < 8) ? nidx9[ko + 1] : N;
                int sz = (nn < N) ? 16 : 0;
                const uint32_t* src = g_mid1p + (size_t)(nn < N ? nn : 0) * 64 + sq * 16;
                uint32_t d = dst_row + ((ko + 1) & 1) * 8704 * 4;
                #pragma unroll
                for (int j = 0; j < 4; j++) cpa16(d + j * 16, src + j * 4, sz);
                CP_COMMIT();
            }
            CP_WAIT1();
            __syncthreads();

            const uint32_t* buf = Asm + (ko & 1) * 8704;
            const uint32_t* Bko = Bsm + ko * 4352;
            #pragma unroll
            for (int s = 0; s < 4; s++) {
                int kl = s * 16;
                AFrag a0 = load_a(buf, 68, m0w, kl, g, tg);
                AFrag a1 = load_a(buf, 68, m0w + 16, kl, g, tg);
                BFrag b0 = load_b(Bko, 68, n0w, kl, g, tg);
                BFrag b1 = load_b(Bko, 68, n0w + 8, kl, g, tg);
                mma3(C[0][0], a0, b0); mma3(C[0][1], a0, b1);
                mma3(C[1][0], a1, b0); mma3(C[1][1], a1, b1);
            }
            __syncthreads();
        }
        #pragma unroll
        for (int mf = 0; mf < 2; mf++)
        #pragma unroll
        for (int nf = 0; nf < 2; nf++) {
            int row = row0 + m0w + mf * 16 + g;
            int col = n0w + nf * 8 + 2 * tg;
            float s0 = __ldg(scale + col), s1 = __ldg(scale + col + 1);
            float bb0 = __ldg(bias + col), bb1 = __ldg(bias + col + 1);
            if (row < N) {
                uint2 o;
                o.x = packf(fmaxf(fmaf(C[mf][nf][0], s0, bb0), 0.f));
                o.y = packf(fmaxf(fmaf(C[mf][nf][1], s1, bb1), 0.f));
                *(uint2*)(g_mid2p + (size_t)row * 64 + col) = o;
            }
            if (row + 8 < N) {
                uint2 o;
                o.x = packf(fmaxf(fmaf(C[mf][nf][2], s0, bb0), 0.f));
                o.y = packf(fmaxf(fmaf(C[mf][nf][3], s1, bb1), 0.f));
                *(uint2*)(g_mid2p + (size_t)(row + 8) * 64 + col) = o;
            }
        }
    }
}

// ===========================================================================
// conv3: cp.async cross-tile prefetch of A (packed mid2), M128 K64 N256.
// smem: B[256][68] (69.6KB) + A 2x[128][68] (69.6KB) = 139,264 B
// ===========================================================================
__global__ void __launch_bounds__(512) conv3_k(
    const float* __restrict__ feat, const float* __restrict__ scale,
    const float* __restrict__ bias, float* __restrict__ out, int N, int tiles)
{
    extern __shared__ uint32_t sm[];
    uint32_t* Bsm = sm;                    // [256][68]
    uint32_t* Asm = sm + 256 * 68;         // 2 x [128][68]
    const uint32_t smb = smem_u32(sm);
    const uint32_t Ab = smb + 256 * 68 * 4;
    const int tid = threadIdx.x, w = tid >> 5, lane = tid & 31;
    const int g = lane >> 2, tg = lane & 3;
    const int m0w = (w & 3) * 32, n0w = (w >> 2) * 64;
    const int sr = tid >> 2, sq = tid & 3;

    for (int e = tid; e < 4096; e += 512) {
        uint4 v = ((const uint4*)g_w3p)[e];
        int n = e >> 4, kq = e & 15;
        *(uint4*)(Bsm + n * 68 + kq * 4) = v;
    }

    const uint32_t dst_row = Ab + (sr * 68 + sq * 16) * 4;
    // prologue: prefetch tile0 A -> buf0
    {
        int grow = (blockIdx.x << 7) + sr;
        int sz = (grow < N) ? 16 : 0;
        const uint32_t* src = g_mid2p + (size_t)(grow < N ? grow : 0) * 64 + sq * 16;
        #pragma unroll
        for (int j = 0; j < 4; j++) cpa16(dst_row + j * 16, src + j * 4, sz);
        CP_COMMIT();
    }

    int cnt = 0;
    for (int t = blockIdx.x; t < tiles; t += gridDim.x) {
        const int row0 = t << 7;
        const int b = cnt & 1;
        {   // prefetch next tile into other buffer (dummy beyond end)
            int grow = ((t + gridDim.x) << 7) + sr;
            int sz = (grow < N) ? 16 : 0;
            const uint32_t* src = g_mid2p + (size_t)(grow < N ? grow : 0) * 64 + sq * 16;
            uint32_t d = dst_row + (b ^ 1) * 8704 * 4;
            #pragma unroll
            for (int j = 0; j < 4; j++) cpa16(d + j * 16, src + j * 4, sz);
            CP_COMMIT();
        }
        CP_WAIT1();
        __syncthreads();

        const uint32_t* buf = Asm + b * 8704;
        float C[2][8][4] = {};
        #pragma unroll
        for (int s = 0; s < 4; s++) {
            int kl = s * 16;
            AFrag a0 = load_a(buf, 68, m0w, kl, g, tg);
            AFrag a1 = load_a(buf, 68, m0w + 16, kl, g, tg);
            #pragma unroll
            for (int nf = 0; nf < 8; nf++) {
                BFrag bb = load_b(Bsm, 68, n0w + nf * 8, kl, g, tg);
                mma3(C[0][nf], a0, bb);
                mma3(C[1][nf], a1, bb);
            }
        }
        #pragma unroll
        for (int mf = 0; mf < 2; mf++)
        #pragma unroll
        for (int nf = 0; nf < 8; nf++) {
            int row = row0 + m0w + mf * 16 + g;
            int col = n0w + nf * 8 + 2 * tg;
            float s0 = __ldg(scale + col), s1 = __ldg(scale + col + 1);
            float bb0 = __ldg(bias + col), bb1 = __ldg(bias + col + 1);
            if (row < N) {
                float2 f = *(const float2*)(feat + (size_t)row * 256 + col);
                float2 o;
                o.x = fmaxf(fmaf(C[mf][nf][0], s0, bb0) + f.x, 0.f);
                o.y = fmaxf(fmaf(C[mf][nf][1], s1, bb1) + f.y, 0.f);
                *(float2*)(out + (size_t)row * 256 + col) = o;
            }
            if (row + 8 < N) {
                float2 f = *(const float2*)(feat + (size_t)(row + 8) * 256 + col);
                float2 o;
                o.x = fmaxf(fmaf(C[mf][nf][2], s0, bb0) + f.x, 0.f);
                o.y = fmaxf(fmaf(C[mf][nf][3], s1, bb1) + f.y, 0.f);
                *(float2*)(out + (size_t)(row + 8) * 256 + col) = o;
            }
        }
        __syncthreads();
        cnt++;
    }
}

// ---------------------------------------------------------------------------
extern "C" void kernel_launch(void* const* d_in, const int* in_sizes, int n_in,
                              void* d_out, int out_size)
{
    const float* feat = (const float*)d_in[0];
    const int*   nbr  = (const int*)  d_in[1];
    const float* w1   = (const float*)d_in[2];
    const float* s1   = (const float*)d_in[3];
    const float* b1   = (const float*)d_in[4];
    const float* w2   = (const float*)d_in[5];
    const float* s2   = (const float*)d_in[6];
    const float* b2   = (const float*)d_in[7];
    const float* w3   = (const float*)d_in[8];
    const float* s3   = (const float*)d_in[9];
    const float* b3   = (const float*)d_in[10];
    float* out = (float*)d_out;

    int N = in_sizes[0] / 256;
    if (N > MAX_N) N = MAX_N;
    int tiles = (N + 127) >> 7;

    const int sm1 = (64 * 260 + 2 * 8704) * 4;     // 136,192
    const int sm2 = (9 * 4352 + 2 * 8704) * 4;     // 226,304
    const int sm3 = (256 * 68 + 2 * 8704) * 4;     // 139,264

    cudaFuncSetAttribute(conv1_k, cudaFuncAttributeMaxDynamicSharedMemorySize, sm1);
    cudaFuncSetAttribute(conv2_k, cudaFuncAttributeMaxDynamicSharedMemorySize, sm2);
    cudaFuncSetAttribute(conv3_k, cudaFuncAttributeMaxDynamicSharedMemorySize, sm3);

    prep_weights<<<64, 256>>>(w1, w2, w3);
    conv1_k<<<296, 512, sm1>>>(feat, s1, b1, N, tiles);
    conv2_k<<<296, 512, sm2>>>(nbr, s2, b2, N, tiles);
    conv3_k<<<296, 512, sm3>>>(feat, s3, b3, out, N, tiles);
}

// round 5
// speedup vs baseline: 1.5127x; 1.5127x over previous
#include <cuda_runtime.h>
#include <cuda_bf16.h>
#include <cstdint>

#define MAX_N 100000

// Split-plane intermediates and weights (hi/lo bf16 planes)
__device__ __align__(16) __nv_bfloat16 g_mid1h[MAX_N * 64];
__device__ __align__(16) __nv_bfloat16 g_mid1l[MAX_N * 64];
__device__ __align__(16) __nv_bfloat16 g_mid2h[MAX_N * 64];
__device__ __align__(16) __nv_bfloat16 g_mid2l[MAX_N * 64];
__device__ __align__(16) __nv_bfloat16 g_w1h[64 * 256], g_w1l[64 * 256];
__device__ __align__(16) __nv_bfloat16 g_w2h[9 * 64 * 64], g_w2l[9 * 64 * 64];
__device__ __align__(16) __nv_bfloat16 g_w3h[256 * 64], g_w3l[256 * 64];

// ---------------- helpers ----------------
__device__ __forceinline__ uint32_t smem_u32(const void* p) {
    uint32_t a;
    asm("{ .reg .u64 t; cvta.to.shared.u64 t, %1; cvt.u32.u64 %0, t; }" : "=r"(a) : "l"(p));
    return a;
}
__device__ __forceinline__ void split2(float a, float b, uint32_t& h, uint32_t& l) {
    __nv_bfloat16 ha = __float2bfloat16(a), hb = __float2bfloat16(b);
    __nv_bfloat16 la = __float2bfloat16(a - __bfloat162float(ha));
    __nv_bfloat16 lb = __float2bfloat16(b - __bfloat162float(hb));
    h = (uint32_t)__bfloat16_as_ushort(ha) | ((uint32_t)__bfloat16_as_ushort(hb) << 16);
    l = (uint32_t)__bfloat16_as_ushort(la) | ((uint32_t)__bfloat16_as_ushort(lb) << 16);
}
__device__ __forceinline__ void cpa16(uint32_t dst, const void* src, int srcsize) {
    asm volatile("cp.async.cg.shared.global [%0], [%1], 16, %2;"
                 :: "r"(dst), "l"(src), "r"(srcsize));
}
#define CP_COMMIT() asm volatile("cp.async.commit_group;" ::: "memory")
#define CP_WAIT1()  asm volatile("cp.async.wait_group 1;" ::: "memory")
#define CP_WAIT0()  asm volatile("cp.async.wait_group 0;" ::: "memory")

__device__ __forceinline__ void mma_bf16(float* c, const uint32_t* a, uint32_t b0, uint32_t b1) {
    asm volatile(
        "mma.sync.aligned.m16n8k16.row.col.f32.bf16.bf16.f32 "
        "{%0,%1,%2,%3}, {%4,%5,%6,%7}, {%8,%9}, {%0,%1,%2,%3};"
        : "+f"(c[0]), "+f"(c[1]), "+f"(c[2]), "+f"(c[3])
        : "r"(a[0]), "r"(a[1]), "r"(a[2]), "r"(a[3]), "r"(b0), "r"(b1));
}
__device__ __forceinline__ void ldsm4(uint32_t* r, uint32_t a) {
    asm volatile("ldmatrix.sync.aligned.m8n8.x4.shared.b16 {%0,%1,%2,%3}, [%4];"
                 : "=r"(r[0]), "=r"(r[1]), "=r"(r[2]), "=r"(r[3]) : "r"(a));
}

struct AF { uint32_t h[4], l[4]; };
struct BF2 { uint32_t h[4], l[4]; };

// A plane: [rows][64 bf16] stride 128B, chunk swizzle c^=row&7. kc0 in {0,2,4,6}.
__device__ __forceinline__ AF load_af(uint32_t hU, uint32_t lU, int lane, int m0, int kc0) {
    int row = m0 + (lane & 15);
    int kc = kc0 + (lane >> 4);
    uint32_t off = row * 128 + (((kc ^ row) & 7)) * 16;
    AF f; ldsm4(f.h, hU + off); ldsm4(f.l, lU + off);
    return f;
}
// B plane: [n rows][K bf16] stride bytes, frags for n0 and n0+8 at {kc0,kc0+1}
__device__ __forceinline__ BF2 load_bf2(uint32_t hU, uint32_t lU, int stride, int lane,
                                        int n0, int kc0) {
    int row = n0 + (lane & 7) + ((lane >> 4) << 3);
    int kc = kc0 + ((lane >> 3) & 1);
    uint32_t off = row * stride + ((kc & ~7) | ((kc ^ row) & 7)) * 16;
    BF2 f; ldsm4(f.h, hU + off); ldsm4(f.l, lU + off);
    return f;
}
// 3-pass bf16 split MMA: hi*hi + hi*lo + lo*hi
__device__ __forceinline__ void mma3v(float* c, const AF& a, uint32_t bh0, uint32_t bh1,
                                      uint32_t bl0, uint32_t bl1) {
    mma_bf16(c, a.h, bh0, bh1);
    mma_bf16(c, a.h, bl0, bl1);
    mma_bf16(c, a.l, bh0, bh1);
}

// ---------------- prep: split weights to hi/lo planes, transpose to [n][k] ----
__global__ void prep_weights(const float* __restrict__ w1, const float* __restrict__ w2,
                             const float* __restrict__ w3) {
    int tid = blockIdx.x * blockDim.x + threadIdx.x;
    int nt = gridDim.x * blockDim.x;
    for (int i = tid; i < 64 * 256; i += nt) {
        int n = i >> 8, k = i & 255;
        float x = w1[k * 64 + n];
        __nv_bfloat16 h = __float2bfloat16(x);
        g_w1h[i] = h; g_w1l[i] = __float2bfloat16(x - __bfloat162float(h));
    }
    for (int i = tid; i < 9 * 64 * 64; i += nt) {
        int ko = i >> 12, n = (i >> 6) & 63, k = i & 63;
        float x = w2[ko * 4096 + k * 64 + n];
        __nv_bfloat16 h = __float2bfloat16(x);
        g_w2h[i] = h; g_w2l[i] = __float2bfloat16(x - __bfloat162float(h));
    }
    for (int i = tid; i < 256 * 64; i += nt) {
        int n = i >> 6, k = i & 63;
        float x = w3[k * 256 + n];
        __nv_bfloat16 h = __float2bfloat16(x);
        g_w3h[i] = h; g_w3l[i] = __float2bfloat16(x - __bfloat162float(h));
    }
}

// ===========================================================================
// conv1: M128 tile, K=256 (4 panels of 64), reg-prefetch pipeline.
// smem: Bh 32KB @0 | Bl 32KB @32768 | A 2 x (Ah 16KB + Al 16KB) @65536 = 128KB
// ===========================================================================
__global__ void __launch_bounds__(512) conv1_k(
    const float* __restrict__ feat, const float* __restrict__ scale,
    const float* __restrict__ bias, int N, int tiles)
{
    extern __shared__ char smem[];
    const uint32_t smU = smem_u32(smem);
    const int tid = threadIdx.x, w = tid >> 5, lane = tid & 31;
    const int g = lane >> 2, tg = lane & 3;
    const int m0w = (w & 3) * 32, n0w = (w >> 2) * 16;
    const int sr = tid >> 2, sq = tid & 3;

    // stage B planes [64][256] with swizzle
    for (int e = tid; e < 2048; e += 512) {
        int n = e >> 5, kc = e & 31;
        int off = n * 512 + ((kc & ~7) | ((kc ^ n) & 7)) * 16;
        *(uint4*)(smem + off)         = *(const uint4*)(g_w1h + n * 256 + kc * 8);
        *(uint4*)(smem + 32768 + off) = *(const uint4*)(g_w1l + n * 256 + kc * 8);
    }

    float4 nx[4];
    {
        int grow = (blockIdx.x << 7) + sr;
        if (grow < N) {
            const float4* s = (const float4*)(feat + (size_t)grow * 256 + sq * 16);
            nx[0] = s[0]; nx[1] = s[1]; nx[2] = s[2]; nx[3] = s[3];
        } else nx[0] = nx[1] = nx[2] = nx[3] = make_float4(0.f, 0.f, 0.f, 0.f);
    }
    __syncthreads();

    for (int t = blockIdx.x; t < tiles; t += gridDim.x) {
        const int row0 = t << 7;
        float C[2][2][4] = {};
        #pragma unroll
        for (int p = 0; p < 4; p++) {
            char* Ah = smem + 65536 + (p & 1) * 32768;
            char* Al = Ah + 16384;
            #pragma unroll
            for (int j = 0; j < 2; j++) {
                float4 u = nx[2 * j], v = nx[2 * j + 1];
                uint4 H, L;
                split2(u.x, u.y, H.x, L.x); split2(u.z, u.w, H.y, L.y);
                split2(v.x, v.y, H.z, L.z); split2(v.z, v.w, H.w, L.w);
                int c = sq * 2 + j;
                int off = sr * 128 + ((c ^ sr) & 7) * 16;
                *(uint4*)(Ah + off) = H; *(uint4*)(Al + off) = L;
            }
            __syncthreads();
            {
                int tn = (p < 3) ? t : t + gridDim.x;
                int pn = (p < 3) ? p + 1 : 0;
                int grow = (tn << 7) + sr;
                if (grow < N) {
                    const float4* s = (const float4*)(feat + (size_t)grow * 256 + pn * 64 + sq * 16);
                    nx[0] = s[0]; nx[1] = s[1]; nx[2] = s[2]; nx[3] = s[3];
                } else nx[0] = nx[1] = nx[2] = nx[3] = make_float4(0.f, 0.f, 0.f, 0.f);
            }
            const uint32_t AhU = smU + 65536 + (p & 1) * 32768, AlU = AhU + 16384;
            #pragma unroll
            for (int s = 0; s < 4; s++) {
                AF a0 = load_af(AhU, AlU, lane, m0w, s * 2);
                AF a1 = load_af(AhU, AlU, lane, m0w + 16, s * 2);
                BF2 b = load_bf2(smU, smU + 32768, 512, lane, n0w, p * 8 + s * 2);
                mma3v(C[0][0], a0, b.h[0], b.h[1], b.l[0], b.l[1]);
                mma3v(C[0][1], a0, b.h[2], b.h[3], b.l[2], b.l[3]);
                mma3v(C[1][0], a1, b.h[0], b.h[1], b.l[0], b.l[1]);
                mma3v(C[1][1], a1, b.h[2], b.h[3], b.l[2], b.l[3]);
            }
        }
        #pragma unroll
        for (int mf = 0; mf < 2; mf++)
        #pragma unroll
        for (int nf = 0; nf < 2; nf++) {
            int row = row0 + m0w + mf * 16 + g;
            int col = n0w + nf * 8 + 2 * tg;
            float s0 = __ldg(scale + col), s1 = __ldg(scale + col + 1);
            float bb0 = __ldg(bias + col), bb1 = __ldg(bias + col + 1);
            if (row < N) {
                uint32_t h, l;
                split2(fmaxf(fmaf(C[mf][nf][0], s0, bb0), 0.f),
                       fmaxf(fmaf(C[mf][nf][1], s1, bb1), 0.f), h, l);
                *(uint32_t*)(g_mid1h + (size_t)row * 64 + col) = h;
                *(uint32_t*)(g_mid1l + (size_t)row * 64 + col) = l;
            }
            if (row + 8 < N) {
                uint32_t h, l;
                split2(fmaxf(fmaf(C[mf][nf][2], s0, bb0), 0.f),
                       fmaxf(fmaf(C[mf][nf][3], s1, bb1), 0.f), h, l);
                *(uint32_t*)(g_mid1h + (size_t)(row + 8) * 64 + col) = h;
                *(uint32_t*)(g_mid1l + (size_t)(row + 8) * 64 + col) = l;
            }
        }
    }
}

// ===========================================================================
// conv2: 9x gathered [128,64]@[64,64], cp.async double-buffered gather.
// smem: B 9 x (Bh 8KB + Bl 8KB) = 144KB @0 | A 2 x (Ah 16KB + Al 16KB) @147456
// total 208KB
// ===========================================================================
__global__ void __launch_bounds__(512) conv2_k(
    const int* __restrict__ nbr, const float* __restrict__ scale,
    const float* __restrict__ bias, int N, int tiles)
{
    extern __shared__ char smem[];
    const uint32_t smU = smem_u32(smem);
    const uint32_t AU = smU + 147456;
    const int tid = threadIdx.x, w = tid >> 5, lane = tid & 31;
    const int g = lane >> 2, tg = lane & 3;
    const int m0w = (w & 3) * 32, n0w = (w >> 2) * 16;
    const int sr = tid >> 2, sq = tid & 3;

    for (int e = tid; e < 4608; e += 512) {
        int ko = e >> 9, r = e & 511, n = r >> 3, kc = r & 7;
        int off = n * 128 + ((kc ^ n) & 7) * 16;
        *(uint4*)(smem + ko * 16384 + off)        = *(const uint4*)(g_w2h + ko * 4096 + n * 64 + kc * 8);
        *(uint4*)(smem + ko * 16384 + 8192 + off) = *(const uint4*)(g_w2l + ko * 4096 + n * 64 + kc * 8);
    }
    __syncthreads();

    const int c0 = sq * 2, c1 = sq * 2 + 1;
    const uint32_t offA0 = sr * 128 + ((c0 ^ sr) & 7) * 16;
    const uint32_t offA1 = sr * 128 + ((c1 ^ sr) & 7) * 16;

    for (int t = blockIdx.x; t < tiles; t += gridDim.x) {
        const int row0 = t << 7;
        const int grow = row0 + sr;
        int nidx9[9];
        #pragma unroll
        for (int ko = 0; ko < 9; ko++)
            nidx9[ko] = (grow < N) ? __ldg(nbr + (size_t)grow * 9 + ko) : N;

        {   // prologue gather ko=0 -> buf0
            int nn = nidx9[0];
            int sz = (nn < N) ? 16 : 0;
            size_t base = (size_t)(nn < N ? nn : 0) * 64;
            cpa16(AU + offA0, g_mid1h + base + c0 * 8, sz);
            cpa16(AU + offA1, g_mid1h + base + c1 * 8, sz);
            cpa16(AU + 16384 + offA0, g_mid1l + base + c0 * 8, sz);
            cpa16(AU + 16384 + offA1, g_mid1l + base + c1 * 8, sz);
            CP_COMMIT();
        }

        float C[2][2][4] = {};
        #pragma unroll
        for (int ko = 0; ko < 9; ko++) {
            if (ko < 8) {
                int nn = nidx9[ko + 1];
                int sz = (nn < N) ? 16 : 0;
                size_t base = (size_t)(nn < N ? nn : 0) * 64;
                uint32_t Ab = AU + ((ko + 1) & 1) * 32768;
                cpa16(Ab + offA0, g_mid1h + base + c0 * 8, sz);
                cpa16(Ab + offA1, g_mid1h + base + c1 * 8, sz);
                cpa16(Ab + 16384 + offA0, g_mid1l + base + c0 * 8, sz);
                cpa16(Ab + 16384 + offA1, g_mid1l + base + c1 * 8, sz);
                CP_COMMIT();
                CP_WAIT1();
            } else {
                CP_WAIT0();
            }
            __syncthreads();

            const uint32_t AhU = AU + (ko & 1) * 32768, AlU = AhU + 16384;
            const uint32_t BhU = smU + ko * 16384, BlU = BhU + 8192;
            #pragma unroll
            for (int s = 0; s < 4; s++) {
                AF a0 = load_af(AhU, AlU, lane, m0w, s * 2);
                AF a1 = load_af(AhU, AlU, lane, m0w + 16, s * 2);
                BF2 b = load_bf2(BhU, BlU, 128, lane, n0w, s * 2);
                mma3v(C[0][0], a0, b.h[0], b.h[1], b.l[0], b.l[1]);
                mma3v(C[0][1], a0, b.h[2], b.h[3], b.l[2], b.l[3]);
                mma3v(C[1][0], a1, b.h[0], b.h[1], b.l[0], b.l[1]);
                mma3v(C[1][1], a1, b.h[2], b.h[3], b.l[2], b.l[3]);
            }
            __syncthreads();
        }
        #pragma unroll
        for (int mf = 0; mf < 2; mf++)
        #pragma unroll
        for (int nf = 0; nf < 2; nf++) {
            int row = row0 + m0w + mf * 16 + g;
            int col = n0w + nf * 8 + 2 * tg;
            float s0 = __ldg(scale + col), s1 = __ldg(scale + col + 1);
            float bb0 = __ldg(bias + col), bb1 = __ldg(bias + col + 1);
            if (row < N) {
                uint32_t h, l;
                split2(fmaxf(fmaf(C[mf][nf][0], s0, bb0), 0.f),
                       fmaxf(fmaf(C[mf][nf][1], s1, bb1), 0.f), h, l);
                *(uint32_t*)(g_mid2h + (size_t)row * 64 + col) = h;
                *(uint32_t*)(g_mid2l + (size_t)row * 64 + col) = l;
            }
            if (row + 8 < N) {
                uint32_t h, l;
                split2(fmaxf(fmaf(C[mf][nf][2], s0, bb0), 0.f),
                       fmaxf(fmaf(C[mf][nf][3], s1, bb1), 0.f), h, l);
                *(uint32_t*)(g_mid2h + (size_t)(row + 8) * 64 + col) = h;
                *(uint32_t*)(g_mid2l + (size_t)(row + 8) * 64 + col) = l;
            }
        }
    }
}

// ===========================================================================
// conv3: M128 K64 N256, cp.async cross-tile A prefetch.
// smem: Bh 32KB @0 | Bl @32768 | A 2 x (16+16KB) @65536 = 128KB
// ===========================================================================
__global__ void __launch_bounds__(512) conv3_k(
    const float* __restrict__ feat, const float* __restrict__ scale,
    const float* __restrict__ bias, float* __restrict__ out, int N, int tiles)
{
    extern __shared__ char smem[];
    const uint32_t smU = smem_u32(smem);
    const uint32_t AU = smU + 65536;
    const int tid = threadIdx.x, w = tid >> 5, lane = tid & 31;
    const int g = lane >> 2, tg = lane & 3;
    const int m0w = (w & 3) * 32, n0w = (w >> 2) * 64;
    const int sr = tid >> 2, sq = tid & 3;

    for (int e = tid; e < 2048; e += 512) {
        int n = e >> 3, kc = e & 7;
        int off = n * 128 + ((kc ^ n) & 7) * 16;
        *(uint4*)(smem + off)         = *(const uint4*)(g_w3h + n * 64 + kc * 8);
        *(uint4*)(smem + 32768 + off) = *(const uint4*)(g_w3l + n * 64 + kc * 8);
    }

    const int c0 = sq * 2, c1 = sq * 2 + 1;
    const uint32_t offA0 = sr * 128 + ((c0 ^ sr) & 7) * 16;
    const uint32_t offA1 = sr * 128 + ((c1 ^ sr) & 7) * 16;

    {   // prologue: prefetch tile0 -> buf0
        int grow = (blockIdx.x << 7) + sr;
        int sz = (grow < N) ? 16 : 0;
        size_t base = (size_t)(grow < N ? grow : 0) * 64;
        cpa16(AU + offA0, g_mid2h + base + c0 * 8, sz);
        cpa16(AU + offA1, g_mid2h + base + c1 * 8, sz);
        cpa16(AU + 16384 + offA0, g_mid2l + base + c0 * 8, sz);
        cpa16(AU + 16384 + offA1, g_mid2l + base + c1 * 8, sz);
        CP_COMMIT();
    }

    int cnt = 0;
    for (int t = blockIdx.x; t < tiles; t += gridDim.x) {
        const int row0 = t << 7;
        const int b = cnt & 1;
        {   // prefetch next tile into other buffer
            int grow = ((t + gridDim.x) << 7) + sr;
            int sz = (grow < N) ? 16 : 0;
            size_t base = (size_t)(grow < N ? grow : 0) * 64;
            uint32_t Ab = AU + (b ^ 1) * 32768;
            cpa16(Ab + offA0, g_mid2h + base + c0 * 8, sz);
            cpa16(Ab + offA1, g_mid2h + base + c1 * 8, sz);
            cpa16(Ab + 16384 + offA0, g_mid2l + base + c0 * 8, sz);
            cpa16(Ab + 16384 + offA1, g_mid2l + base + c1 * 8, sz);
            CP_COMMIT();
        }
        CP_WAIT1();
        __syncthreads();

        const uint32_t AhU = AU + b * 32768, AlU = AhU + 16384;
        float C[2][8][4] = {};
        #pragma unroll
        for (int s = 0; s < 4; s++) {
            AF a0 = load_af(AhU, AlU, lane, m0w, s * 2);
            AF a1 = load_af(AhU, AlU, lane, m0w + 16, s * 2);
            #pragma unroll
            for (int nb = 0; nb < 4; nb++) {
                BF2 bb = load_bf2(smU, smU + 32768, 128, lane, n0w + nb * 16, s * 2);
                mma3v(C[0][2 * nb],     a0, bb.h[0], bb.h[1], bb.l[0], bb.l[1]);
                mma3v(C[0][2 * nb + 1], a0, bb.h[2], bb.h[3], bb.l[2], bb.l[3]);
                mma3v(C[1][2 * nb],     a1, bb.h[0], bb.h[1], bb.l[0], bb.l[1]);
                mma3v(C[1][2 * nb + 1], a1, bb.h[2], bb.h[3], bb.l[2], bb.l[3]);
            }
        }
        #pragma unroll
        for (int mf = 0; mf < 2; mf++)
        #pragma unroll
        for (int nf = 0; nf < 8; nf++) {
            int row = row0 + m0w + mf * 16 + g;
            int col = n0w + nf * 8 + 2 * tg;
            float s0 = __ldg(scale + col), s1 = __ldg(scale + col + 1);
            float bb0 = __ldg(bias + col), bb1 = __ldg(bias + col + 1);
            if (row < N) {
                float2 f = *(const float2*)(feat + (size_t)row * 256 + col);
                float2 o;
                o.x = fmaxf(fmaf(C[mf][nf][0], s0, bb0) + f.x, 0.f);
                o.y = fmaxf(fmaf(C[mf][nf][1], s1, bb1) + f.y, 0.f);
                *(float2*)(out + (size_t)row * 256 + col) = o;
            }
            if (row + 8 < N) {
                float2 f = *(const float2*)(feat + (size_t)(row + 8) * 256 + col);
                float2 o;
                o.x = fmaxf(fmaf(C[mf][nf][2], s0, bb0) + f.x, 0.f);
                o.y = fmaxf(fmaf(C[mf][nf][3], s1, bb1) + f.y, 0.f);
                *(float2*)(out + (size_t)(row + 8) * 256 + col) = o;
            }
        }
        __syncthreads();
        cnt++;
    }
}

// ---------------------------------------------------------------------------
extern "C" void kernel_launch(void* const* d_in, const int* in_sizes, int n_in,
                              void* d_out, int out_size)
{
    const float* feat = (const float*)d_in[0];
    const int*   nbr  = (const int*)  d_in[1];
    const float* w1   = (const float*)d_in[2];
    const float* s1   = (const float*)d_in[3];
    const float* b1   = (const float*)d_in[4];
    const float* w2   = (const float*)d_in[5];
    const float* s2   = (const float*)d_in[6];
    const float* b2   = (const float*)d_in[7];
    const float* w3   = (const float*)d_in[8];
    const float* s3   = (const float*)d_in[9];
    const float* b3   = (const float*)d_in[10];
    float* out = (float*)d_out;

    int N = in_sizes[0] / 256;
    if (N > MAX_N) N = MAX_N;
    int tiles = (N + 127) >> 7;

    const int sm1 = 131072;
    const int sm2 = 212992;
    const int sm3 = 131072;

    cudaFuncSetAttribute(conv1_k, cudaFuncAttributeMaxDynamicSharedMemorySize, sm1);
    cudaFuncSetAttribute(conv2_k, cudaFuncAttributeMaxDynamicSharedMemorySize, sm2);
    cudaFuncSetAttribute(conv3_k, cudaFuncAttributeMaxDynamicSharedMemorySize, sm3);

    prep_weights<<<64, 256>>>(w1, w2, w3);
    conv1_k<<<148, 512, sm1>>>(feat, s1, b1, N, tiles);
    conv2_k<<<148, 512, sm2>>>(nbr, s2, b2, N, tiles);
    conv3_k<<<148, 512, sm3>>>(feat, s3, b3, out, N, tiles);
}

// round 6
// speedup vs baseline: 1.6198x; 1.0708x over previous
#include <cuda_runtime.h>
#include <cuda_bf16.h>
#include <cstdint>

#define MAX_N 100000

// Split-plane intermediates and weights (hi/lo bf16 planes)
__device__ __align__(16) __nv_bfloat16 g_mid1h[MAX_N * 64];
__device__ __align__(16) __nv_bfloat16 g_mid1l[MAX_N * 64];
__device__ __align__(16) __nv_bfloat16 g_mid2h[MAX_N * 64];
__device__ __align__(16) __nv_bfloat16 g_mid2l[MAX_N * 64];
__device__ __align__(16) __nv_bfloat16 g_w1h[64 * 256], g_w1l[64 * 256];
__device__ __align__(16) __nv_bfloat16 g_w2h[9 * 64 * 64], g_w2l[9 * 64 * 64];
__device__ __align__(16) __nv_bfloat16 g_w3h[256 * 64], g_w3l[256 * 64];

// ---------------- helpers ----------------
__device__ __forceinline__ uint32_t smem_u32(const void* p) {
    uint32_t a;
    asm("{ .reg .u64 t; cvta.to.shared.u64 t, %1; cvt.u32.u64 %0, t; }" : "=r"(a) : "l"(p));
    return a;
}
__device__ __forceinline__ void split2(float a, float b, uint32_t& h, uint32_t& l) {
    __nv_bfloat16 ha = __float2bfloat16(a), hb = __float2bfloat16(b);
    __nv_bfloat16 la = __float2bfloat16(a - __bfloat162float(ha));
    __nv_bfloat16 lb = __float2bfloat16(b - __bfloat162float(hb));
    h = (uint32_t)__bfloat16_as_ushort(ha) | ((uint32_t)__bfloat16_as_ushort(hb) << 16);
    l = (uint32_t)__bfloat16_as_ushort(la) | ((uint32_t)__bfloat16_as_ushort(lb) << 16);
}
__device__ __forceinline__ void cpa16(uint32_t dst, const void* src, int srcsize) {
    asm volatile("cp.async.cg.shared.global [%0], [%1], 16, %2;"
                 :: "r"(dst), "l"(src), "r"(srcsize));
}
#define CP_COMMIT() asm volatile("cp.async.commit_group;" ::: "memory")
#define CP_WAIT1()  asm volatile("cp.async.wait_group 1;" ::: "memory")
#define CP_WAIT0()  asm volatile("cp.async.wait_group 0;" ::: "memory")

__device__ __forceinline__ void mma_bf16(float* c, const uint32_t* a, uint32_t b0, uint32_t b1) {
    asm volatile(
        "mma.sync.aligned.m16n8k16.row.col.f32.bf16.bf16.f32 "
        "{%0,%1,%2,%3}, {%4,%5,%6,%7}, {%8,%9}, {%0,%1,%2,%3};"
        : "+f"(c[0]), "+f"(c[1]), "+f"(c[2]), "+f"(c[3])
        : "r"(a[0]), "r"(a[1]), "r"(a[2]), "r"(a[3]), "r"(b0), "r"(b1));
}
__device__ __forceinline__ void ldsm4(uint32_t* r, uint32_t a) {
    asm volatile("ldmatrix.sync.aligned.m8n8.x4.shared.b16 {%0,%1,%2,%3}, [%4];"
                 : "=r"(r[0]), "=r"(r[1]), "=r"(r[2]), "=r"(r[3]) : "r"(a));
}

struct AF { uint32_t h[4], l[4]; };
struct BF2 { uint32_t h[4], l[4]; };

// A plane: [rows][64 bf16] stride 128B, chunk swizzle c^=row&7. kc0 in {0,2,4,6}.
__device__ __forceinline__ AF load_af(uint32_t hU, uint32_t lU, int lane, int m0, int kc0) {
    int row = m0 + (lane & 15);
    int kc = kc0 + (lane >> 4);
    uint32_t off = row * 128 + (((kc ^ row) & 7)) * 16;
    AF f; ldsm4(f.h, hU + off); ldsm4(f.l, lU + off);
    return f;
}
// B plane: [n rows][K bf16] stride bytes, frags for n0 and n0+8 at {kc0,kc0+1}
__device__ __forceinline__ BF2 load_bf2(uint32_t hU, uint32_t lU, int stride, int lane,
                                        int n0, int kc0) {
    int row = n0 + (lane & 7) + ((lane >> 4) << 3);
    int kc = kc0 + ((lane >> 3) & 1);
    uint32_t off = row * stride + ((kc & ~7) | ((kc ^ row) & 7)) * 16;
    BF2 f; ldsm4(f.h, hU + off); ldsm4(f.l, lU + off);
    return f;
}
// 3-pass bf16 split MMA: hi*hi + hi*lo + lo*hi
__device__ __forceinline__ void mma3v(float* c, const AF& a, uint32_t bh0, uint32_t bh1,
                                      uint32_t bl0, uint32_t bl1) {
    mma_bf16(c, a.h, bh0, bh1);
    mma_bf16(c, a.h, bl0, bl1);
    mma_bf16(c, a.l, bh0, bh1);
}

// ---------------- prep: split weights to hi/lo planes, transpose to [n][k] ----
__global__ void prep_weights(const float* __restrict__ w1, const float* __restrict__ w2,
                             const float* __restrict__ w3) {
    int tid = blockIdx.x * blockDim.x + threadIdx.x;
    int nt = gridDim.x * blockDim.x;
    for (int i = tid; i < 64 * 256; i += nt) {
        int n = i >> 8, k = i & 255;
        float x = w1[k * 64 + n];
        __nv_bfloat16 h = __float2bfloat16(x);
        g_w1h[i] = h; g_w1l[i] = __float2bfloat16(x - __bfloat162float(h));
    }
    for (int i = tid; i < 9 * 64 * 64; i += nt) {
        int ko = i >> 12, n = (i >> 6) & 63, k = i & 63;
        float x = w2[ko * 4096 + k * 64 + n];
        __nv_bfloat16 h = __float2bfloat16(x);
        g_w2h[i] = h; g_w2l[i] = __float2bfloat16(x - __bfloat162float(h));
    }
    for (int i = tid; i < 256 * 64; i += nt) {
        int n = i >> 6, k = i & 63;
        float x = w3[k * 256 + n];
        __nv_bfloat16 h = __float2bfloat16(x);
        g_w3h[i] = h; g_w3l[i] = __float2bfloat16(x - __bfloat162float(h));
    }
}

// ===========================================================================
// conv1: M64 tiles, K=256 (4 panels of 64), 256 thr, 2 CTAs/SM.
// smem: Bh 32KB @0 | Bl 32KB @32768 | A 2buf x (Ah 8KB + Al 8KB) @65536 = 96KB
// 8 warps: m0w=(w&1)*32, n0w=(w>>1)*16
// ===========================================================================
__global__ void __launch_bounds__(256, 2) conv1_k(
    const float* __restrict__ feat, const float* __restrict__ scale,
    const float* __restrict__ bias, int N, int tiles)
{
    extern __shared__ char smem[];
    const uint32_t smU = smem_u32(smem);
    const int tid = threadIdx.x, w = tid >> 5, lane = tid & 31;
    const int g = lane >> 2, tg = lane & 3;
    const int m0w = (w & 1) * 32, n0w = (w >> 1) * 16;
    const int sr = tid >> 2, sq = tid & 3;   // 64 rows x 4 chunks of 16 floats

    // stage B planes [64][256] with swizzle
    for (int e = tid; e < 2048; e += 256) {
        int n = e >> 5, kc = e & 31;
        int off = n * 512 + ((kc & ~7) | ((kc ^ n) & 7)) * 16;
        *(uint4*)(smem + off)         = *(const uint4*)(g_w1h + n * 256 + kc * 8);
        *(uint4*)(smem + 32768 + off) = *(const uint4*)(g_w1l + n * 256 + kc * 8);
    }

    float4 nx[4];
    {
        int grow = (blockIdx.x << 6) + sr;
        if (grow < N) {
            const float4* s = (const float4*)(feat + (size_t)grow * 256 + sq * 16);
            nx[0] = s[0]; nx[1] = s[1]; nx[2] = s[2]; nx[3] = s[3];
        } else nx[0] = nx[1] = nx[2] = nx[3] = make_float4(0.f, 0.f, 0.f, 0.f);
    }
    __syncthreads();

    for (int t = blockIdx.x; t < tiles; t += gridDim.x) {
        const int row0 = t << 6;
        float C[2][2][4] = {};
        #pragma unroll
        for (int p = 0; p < 4; p++) {
            char* Ah = smem + 65536 + (p & 1) * 16384;
            char* Al = Ah + 8192;
            #pragma unroll
            for (int j = 0; j < 2; j++) {
                float4 u = nx[2 * j], v = nx[2 * j + 1];
                uint4 H, L;
                split2(u.x, u.y, H.x, L.x); split2(u.z, u.w, H.y, L.y);
                split2(v.x, v.y, H.z, L.z); split2(v.z, v.w, H.w, L.w);
                int c = sq * 2 + j;
                int off = sr * 128 + ((c ^ sr) & 7) * 16;
                *(uint4*)(Ah + off) = H; *(uint4*)(Al + off) = L;
            }
            __syncthreads();
            {
                int tn = (p < 3) ? t : t + gridDim.x;
                int pn = (p < 3) ? p + 1 : 0;
                int grow = (tn << 6) + sr;
                if (grow < N) {
                    const float4* s = (const float4*)(feat + (size_t)grow * 256 + pn * 64 + sq * 16);
                    nx[0] = s[0]; nx[1] = s[1]; nx[2] = s[2]; nx[3] = s[3];
                } else nx[0] = nx[1] = nx[2] = nx[3] = make_float4(0.f, 0.f, 0.f, 0.f);
            }
            const uint32_t AhU = smU + 65536 + (p & 1) * 16384, AlU = AhU + 8192;
            #pragma unroll
            for (int s = 0; s < 4; s++) {
                AF a0 = load_af(AhU, AlU, lane, m0w, s * 2);
                AF a1 = load_af(AhU, AlU, lane, m0w + 16, s * 2);
                BF2 b = load_bf2(smU, smU + 32768, 512, lane, n0w, p * 8 + s * 2);
                mma3v(C[0][0], a0, b.h[0], b.h[1], b.l[0], b.l[1]);
                mma3v(C[0][1], a0, b.h[2], b.h[3], b.l[2], b.l[3]);
                mma3v(C[1][0], a1, b.h[0], b.h[1], b.l[0], b.l[1]);
                mma3v(C[1][1], a1, b.h[2], b.h[3], b.l[2], b.l[3]);
            }
        }
        #pragma unroll
        for (int mf = 0; mf < 2; mf++)
        #pragma unroll
        for (int nf = 0; nf < 2; nf++) {
            int row = row0 + m0w + mf * 16 + g;
            int col = n0w + nf * 8 + 2 * tg;
            float s0 = __ldg(scale + col), s1 = __ldg(scale + col + 1);
            float bb0 = __ldg(bias + col), bb1 = __ldg(bias + col + 1);
            if (row < N) {
                uint32_t h, l;
                split2(fmaxf(fmaf(C[mf][nf][0], s0, bb0), 0.f),
                       fmaxf(fmaf(C[mf][nf][1], s1, bb1), 0.f), h, l);
                *(uint32_t*)(g_mid1h + (size_t)row * 64 + col) = h;
                *(uint32_t*)(g_mid1l + (size_t)row * 64 + col) = l;
            }
            if (row + 8 < N) {
                uint32_t h, l;
                split2(fmaxf(fmaf(C[mf][nf][2], s0, bb0), 0.f),
                       fmaxf(fmaf(C[mf][nf][3], s1, bb1), 0.f), h, l);
                *(uint32_t*)(g_mid1h + (size_t)(row + 8) * 64 + col) = h;
                *(uint32_t*)(g_mid1l + (size_t)(row + 8) * 64 + col) = l;
            }
        }
    }
}

// ===========================================================================
// conv2: 9x gathered [128,64]@[64,64], double-buffered gather, ONE sync per ko.
// smem: B 9 x 16KB = 144KB @0 | A 2 x (16+16KB) @147456 = 208KB, 512 thr.
// ===========================================================================
__global__ void __launch_bounds__(512) conv2_k(
    const int* __restrict__ nbr, const float* __restrict__ scale,
    const float* __restrict__ bias, int N, int tiles)
{
    extern __shared__ char smem[];
    const uint32_t smU = smem_u32(smem);
    const uint32_t AU = smU + 147456;
    const int tid = threadIdx.x, w = tid >> 5, lane = tid & 31;
    const int g = lane >> 2, tg = lane & 3;
    const int m0w = (w & 3) * 32, n0w = (w >> 2) * 16;
    const int sr = tid >> 2, sq = tid & 3;

    for (int e = tid; e < 4608; e += 512) {
        int ko = e >> 9, r = e & 511, n = r >> 3, kc = r & 7;
        int off = n * 128 + ((kc ^ n) & 7) * 16;
        *(uint4*)(smem + ko * 16384 + off)        = *(const uint4*)(g_w2h + ko * 4096 + n * 64 + kc * 8);
        *(uint4*)(smem + ko * 16384 + 8192 + off) = *(const uint4*)(g_w2l + ko * 4096 + n * 64 + kc * 8);
    }
    __syncthreads();

    const int c0 = sq * 2, c1 = sq * 2 + 1;
    const uint32_t offA0 = sr * 128 + ((c0 ^ sr) & 7) * 16;
    const uint32_t offA1 = sr * 128 + ((c1 ^ sr) & 7) * 16;

    for (int t = blockIdx.x; t < tiles; t += gridDim.x) {
        const int row0 = t << 7;
        const int grow = row0 + sr;
        int nidx9[9];
        #pragma unroll
        for (int ko = 0; ko < 9; ko++)
            nidx9[ko] = (grow < N) ? __ldg(nbr + (size_t)grow * 9 + ko) : N;

        {   // prologue gather ko=0 -> buf0
            int nn = nidx9[0];
            int sz = (nn < N) ? 16 : 0;
            size_t base = (size_t)(nn < N ? nn : 0) * 64;
            cpa16(AU + offA0, g_mid1h + base + c0 * 8, sz);
            cpa16(AU + offA1, g_mid1h + base + c1 * 8, sz);
            cpa16(AU + 16384 + offA0, g_mid1l + base + c0 * 8, sz);
            cpa16(AU + 16384 + offA1, g_mid1l + base + c1 * 8, sz);
            CP_COMMIT();
        }

        float C[2][2][4] = {};
        #pragma unroll
        for (int ko = 0; ko < 9; ko++) {
            CP_WAIT0();              // this thread's gather ko landed
            __syncthreads();         // everyone's gather ko visible; MMA ko-1 done
            if (ko < 8) {            // issue gather ko+1 (overlaps MMA ko)
                int nn = nidx9[ko + 1];
                int sz = (nn < N) ? 16 : 0;
                size_t base = (size_t)(nn < N ? nn : 0) * 64;
                uint32_t Ab = AU + ((ko + 1) & 1) * 32768;
                cpa16(Ab + offA0, g_mid1h + base + c0 * 8, sz);
                cpa16(Ab + offA1, g_mid1h + base + c1 * 8, sz);
                cpa16(Ab + 16384 + offA0, g_mid1l + base + c0 * 8, sz);
                cpa16(Ab + 16384 + offA1, g_mid1l + base + c1 * 8, sz);
                CP_COMMIT();
            }
            const uint32_t AhU = AU + (ko & 1) * 32768, AlU = AhU + 16384;
            const uint32_t BhU = smU + ko * 16384, BlU = BhU + 8192;
            #pragma unroll
            for (int s = 0; s < 4; s++) {
                AF a0 = load_af(AhU, AlU, lane, m0w, s * 2);
                AF a1 = load_af(AhU, AlU, lane, m0w + 16, s * 2);
                BF2 b = load_bf2(BhU, BlU, 128, lane, n0w, s * 2);
                mma3v(C[0][0], a0, b.h[0], b.h[1], b.l[0], b.l[1]);
                mma3v(C[0][1], a0, b.h[2], b.h[3], b.l[2], b.l[3]);
                mma3v(C[1][0], a1, b.h[0], b.h[1], b.l[0], b.l[1]);
                mma3v(C[1][1], a1, b.h[2], b.h[3], b.l[2], b.l[3]);
            }
        }
        #pragma unroll
        for (int mf = 0; mf < 2; mf++)
        #pragma unroll
        for (int nf = 0; nf < 2; nf++) {
            int row = row0 + m0w + mf * 16 + g;
            int col = n0w + nf * 8 + 2 * tg;
            float s0 = __ldg(scale + col), s1 = __ldg(scale + col + 1);
            float bb0 = __ldg(bias + col), bb1 = __ldg(bias + col + 1);
            if (row < N) {
                uint32_t h, l;
                split2(fmaxf(fmaf(C[mf][nf][0], s0, bb0), 0.f),
                       fmaxf(fmaf(C[mf][nf][1], s1, bb1), 0.f), h, l);
                *(uint32_t*)(g_mid2h + (size_t)row * 64 + col) = h;
                *(uint32_t*)(g_mid2l + (size_t)row * 64 + col) = l;
            }
            if (row + 8 < N) {
                uint32_t h, l;
                split2(fmaxf(fmaf(C[mf][nf][2], s0, bb0), 0.f),
                       fmaxf(fmaf(C[mf][nf][3], s1, bb1), 0.f), h, l);
                *(uint32_t*)(g_mid2h + (size_t)(row + 8) * 64 + col) = h;
                *(uint32_t*)(g_mid2l + (size_t)(row + 8) * 64 + col) = l;
            }
        }
        __syncthreads();   // protect buf0 before next tile's prologue gather
    }
}

// ===========================================================================
// conv3: M128 K64, N-split into two 128-col halves; 256 thr, 2 CTAs/SM.
// smem: Bh 16KB @0 | Bl @16384 | A 2buf x (16+16KB) @32768 = 96KB
// 8 warps: m0w=(w&3)*32, n0 local=(w>>2)*64
// ===========================================================================
__global__ void __launch_bounds__(256, 2) conv3_k(
    const float* __restrict__ feat, const float* __restrict__ scale,
    const float* __restrict__ bias, float* __restrict__ out, int N, int tiles)
{
    extern __shared__ char smem[];
    const uint32_t smU = smem_u32(smem);
    const uint32_t AU = smU + 32768;
    const int tid = threadIdx.x, w = tid >> 5, lane = tid & 31;
    const int g = lane >> 2, tg = lane & 3;
    const int nhalf = blockIdx.x & 1;
    const int t0 = blockIdx.x >> 1, tstep = gridDim.x >> 1;
    const int m0w = (w & 3) * 32, n0l = (w >> 2) * 64;
    const int colbase = nhalf * 128;
    const int sr = tid >> 1, sq = tid & 1;   // 128 rows x 2 half-rows

    // stage this half's B planes: local rows 0..127 = global n = colbase+r
    for (int e = tid; e < 1024; e += 256) {
        int n = e >> 3, kc = e & 7;
        int off = n * 128 + ((kc ^ n) & 7) * 16;
        *(uint4*)(smem + off)         = *(const uint4*)(g_w3h + (colbase + n) * 64 + kc * 8);
        *(uint4*)(smem + 16384 + off) = *(const uint4*)(g_w3l + (colbase + n) * 64 + kc * 8);
    }

    {   // prologue: prefetch tile t0 -> buf0
        int grow = (t0 << 7) + sr;
        int sz = (grow < N) ? 16 : 0;
        size_t base = (size_t)(grow < N ? grow : 0) * 64;
        #pragma unroll
        for (int j = 0; j < 4; j++) {
            int c = sq * 4 + j;
            uint32_t off = sr * 128 + ((c ^ sr) & 7) * 16;
            cpa16(AU + off, g_mid2h + base + c * 8, sz);
            cpa16(AU + 16384 + off, g_mid2l + base + c * 8, sz);
        }
        CP_COMMIT();
    }

    int cnt = 0;
    for (int t = t0; t < tiles; t += tstep) {
        const int row0 = t << 7;
        const int b = cnt & 1;
        {   // prefetch next tile into other buffer
            int grow = ((t + tstep) << 7) + sr;
            int sz = (grow < N) ? 16 : 0;
            size_t base = (size_t)(grow < N ? grow : 0) * 64;
            uint32_t Ab = AU + (b ^ 1) * 32768;
            #pragma unroll
            for (int j = 0; j < 4; j++) {
                int c = sq * 4 + j;
                uint32_t off = sr * 128 + ((c ^ sr) & 7) * 16;
                cpa16(Ab + off, g_mid2h + base + c * 8, sz);
                cpa16(Ab + 16384 + off, g_mid2l + base + c * 8, sz);
            }
            CP_COMMIT();
        }
        CP_WAIT1();
        __syncthreads();

        const uint32_t AhU = AU + b * 32768, AlU = AhU + 16384;
        float C[2][8][4] = {};
        #pragma unroll
        for (int s = 0; s < 4; s++) {
            AF a0 = load_af(AhU, AlU, lane, m0w, s * 2);
            AF a1 = load_af(AhU, AlU, lane, m0w + 16, s * 2);
            #pragma unroll
            for (int nb = 0; nb < 4; nb++) {
                BF2 bb = load_bf2(smU, smU + 16384, 128, lane, n0l + nb * 16, s * 2);
                mma3v(C[0][2 * nb],     a0, bb.h[0], bb.h[1], bb.l[0], bb.l[1]);
                mma3v(C[0][2 * nb + 1], a0, bb.h[2], bb.h[3], bb.l[2], bb.l[3]);
                mma3v(C[1][2 * nb],     a1, bb.h[0], bb.h[1], bb.l[0], bb.l[1]);
                mma3v(C[1][2 * nb + 1], a1, bb.h[2], bb.h[3], bb.l[2], bb.l[3]);
            }
        }
        #pragma unroll
        for (int mf = 0; mf < 2; mf++)
        #pragma unroll
        for (int nf = 0; nf < 8; nf++) {
            int row = row0 + m0w + mf * 16 + g;
            int col = colbase + n0l + nf * 8 + 2 * tg;
            float s0 = __ldg(scale + col), s1 = __ldg(scale + col + 1);
            float bb0 = __ldg(bias + col), bb1 = __ldg(bias + col + 1);
            if (row < N) {
                float2 f = *(const float2*)(feat + (size_t)row * 256 + col);
                float2 o;
                o.x = fmaxf(fmaf(C[mf][nf][0], s0, bb0) + f.x, 0.f);
                o.y = fmaxf(fmaf(C[mf][nf][1], s1, bb1) + f.y, 0.f);
                *(float2*)(out + (size_t)row * 256 + col) = o;
            }
            if (row + 8 < N) {
                float2 f = *(const float2*)(feat + (size_t)(row + 8) * 256 + col);
                float2 o;
                o.x = fmaxf(fmaf(C[mf][nf][2], s0, bb0) + f.x, 0.f);
                o.y = fmaxf(fmaf(C[mf][nf][3], s1, bb1) + f.y, 0.f);
                *(float2*)(out + (size_t)(row + 8) * 256 + col) = o;
            }
        }
        __syncthreads();
        cnt++;
    }
}

// ---------------------------------------------------------------------------
extern "C" void kernel_launch(void* const* d_in, const int* in_sizes, int n_in,
                              void* d_out, int out_size)
{
    const float* feat = (const float*)d_in[0];
    const int*   nbr  = (const int*)  d_in[1];
    const float* w1   = (const float*)d_in[2];
    const float* s1   = (const float*)d_in[3];
    const float* b1   = (const float*)d_in[4];
    const float* w2   = (const float*)d_in[5];
    const float* s2   = (const float*)d_in[6];
    const float* b2   = (const float*)d_in[7];
    const float* w3   = (const float*)d_in[8];
    const float* s3   = (const float*)d_in[9];
    const float* b3   = (const float*)d_in[10];
    float* out = (float*)d_out;

    int N = in_sizes[0] / 256;
    if (N > MAX_N) N = MAX_N;
    int tiles128 = (N + 127) >> 7;
    int tiles64  = (N + 63) >> 6;

    const int sm1 = 98304;    // 96KB -> 2 CTAs/SM
    const int sm2 = 212992;   // 208KB -> 1 CTA/SM
    const int sm3 = 98304;    // 96KB -> 2 CTAs/SM

    cudaFuncSetAttribute(conv1_k, cudaFuncAttributeMaxDynamicSharedMemorySize, sm1);
    cudaFuncSetAttribute(conv2_k, cudaFuncAttributeMaxDynamicSharedMemorySize, sm2);
    cudaFuncSetAttribute(conv3_k, cudaFuncAttributeMaxDynamicSharedMemorySize, sm3);

    prep_weights<<<64, 256>>>(w1, w2, w3);
    conv1_k<<<296, 256, sm1>>>(feat, s1, b1, N, tiles64);
    conv2_k<<<148, 512, sm2>>>(nbr, s2, b2, N, tiles128);
    conv3_k<<<296, 256, sm3>>>(feat, s3, b3, out, N, tiles128);
}